// round 6
// baseline (speedup 1.0000x reference)
#include <cuda_runtime.h>
#include <cuda_bf16.h>

// ---------------- problem constants ----------------
#define N_NODES  262144
#define N_EDGES  1048576
#define N_GRAPHS 8192
#define F_IN     64
#define UNITS    64
#define ADDUCT   8
#define DENSE    512

typedef unsigned long long ULL;

// ---------------- scratch (static device globals; no allocation) ----------------
__device__ __align__(16) float g_t[N_NODES * UNITS];
__device__ __align__(16) float g_h[N_NODES * UNITS];
__device__ __align__(16) int   g_cnt[N_NODES];
__device__ __align__(16) int   g_rowptr[N_NODES + 16];
__device__ __align__(16) int   g_cursor[N_NODES];
__device__ __align__(16) int   g_col[N_EDGES];
__device__ __align__(16) float g_wgt[N_EDGES];
__device__ __align__(16) int   g_bsum[256];
__device__ __align__(16) int   g_boff[256];
__device__ __align__(16) int   g_start[N_GRAPHS + 16];
__device__ __align__(16) float g_xcat[N_GRAPHS * (UNITS + ADDUCT)];
__device__ __align__(16) float g_z1[N_GRAPHS * DENSE];
__device__ __align__(16) float g_z2[N_GRAPHS * DENSE];

// ---------------- f32x2 helpers (Blackwell packed fp32) ----------------
__device__ __forceinline__ ULL pack2(float lo, float hi) {
    ULL r; asm("mov.b64 %0, {%1, %2};" : "=l"(r) : "f"(lo), "f"(hi)); return r;
}
__device__ __forceinline__ void unpack2(ULL v, float& lo, float& hi) {
    asm("mov.b64 {%0, %1}, %2;" : "=f"(lo), "=f"(hi) : "l"(v));
}
__device__ __forceinline__ ULL fma2(ULL a, ULL b, ULL c) {
    ULL d; asm("fma.rn.f32x2 %0, %1, %2, %3;" : "=l"(d) : "l"(a), "l"(b), "l"(c)); return d;
}

// ---------------- degree count ----------------
__global__ void count_deg_kernel(const int* __restrict__ dst, int* __restrict__ cnt) {
    int e = blockIdx.x * blockDim.x + threadIdx.x;
    if (e < N_EDGES) atomicAdd(&cnt[dst[e]], 1);
}

// ---------------- exclusive scan of 262144 ints (3 kernels) ----------------
__global__ void scan_block_kernel(const int* __restrict__ cnt, int* __restrict__ pref,
                                  int* __restrict__ bsum) {
    __shared__ int s[1024];
    int tid = threadIdx.x;
    int i = blockIdx.x * 1024 + tid;
    int v = cnt[i];
    s[tid] = v;
    __syncthreads();
    for (int off = 1; off < 1024; off <<= 1) {
        int add = (tid >= off) ? s[tid - off] : 0;
        __syncthreads();
        s[tid] += add;
        __syncthreads();
    }
    pref[i] = s[tid] - v;                 // exclusive prefix within block
    if (tid == 1023) bsum[blockIdx.x] = s[1023];
}

__global__ void scan_sums_kernel(const int* __restrict__ bsum, int* __restrict__ boff) {
    __shared__ int s[256];
    int tid = threadIdx.x;
    int v = bsum[tid];
    s[tid] = v;
    __syncthreads();
    for (int off = 1; off < 256; off <<= 1) {
        int add = (tid >= off) ? s[tid - off] : 0;
        __syncthreads();
        s[tid] += add;
        __syncthreads();
    }
    boff[tid] = s[tid] - v;
}

__global__ void scan_apply_kernel(int* __restrict__ rowptr, const int* __restrict__ boff,
                                  int* __restrict__ cursor) {
    int i = blockIdx.x * blockDim.x + threadIdx.x;
    int v = rowptr[i] + boff[i >> 10];
    rowptr[i] = v;
    cursor[i] = v;
    if (i == 0) rowptr[N_NODES] = N_EDGES;
}

// ---------------- CSR fill (bucket edges by dst) + edge weights ----------------
__global__ void fill_csr_kernel(const int* __restrict__ src, const int* __restrict__ dst,
                                const int* __restrict__ cnt, int* __restrict__ cursor,
                                int* __restrict__ col, float* __restrict__ wgt) {
    int e = blockIdx.x * blockDim.x + threadIdx.x;
    if (e >= N_EDGES) return;
    int s = src[e], d = dst[e];
    float ds = (float)cnt[s] + 1.0f;
    float dd = (float)cnt[d] + 1.0f;
    float nrm = rsqrtf(ds * dd);
    int pos = atomicAdd(&cursor[d], 1);
    col[pos] = s;
    wgt[pos] = nrm;
}

// ---------------- graph segment starts (graph_ids sorted) ----------------
__global__ void graph_starts_kernel(const int* __restrict__ gid, int* __restrict__ start) {
    int n = blockIdx.x * blockDim.x + threadIdx.x;
    if (n >= N_NODES) return;
    int g = gid[n];
    int gp = (n == 0) ? -1 : gid[n - 1];
    for (int gg = gp + 1; gg <= g; gg++) start[gg] = n;
    if (n == N_NODES - 1) {
        for (int gg = g + 1; gg <= N_GRAPHS; gg++) start[gg] = N_NODES;
    }
}

// ---------------- fp32 SGEMM: C = (A[M,K] @ B[K,N]) + bias, optional relu ----------------
// BM x BN tile per block, 8x8 micro-tile per thread, rows packed in f32x2 lanes.
template <int BM, int BN, bool RELU>
__global__ void sgemm_kernel(const float* __restrict__ A, const float* __restrict__ B,
                             const float* __restrict__ bias, float* __restrict__ C,
                             int K, int N) {
    constexpr int BK  = 8;
    constexpr int NCG = BN / 8;
    constexpr int NRG = BM / 8;
    constexpr int NT  = NCG * NRG;
    static_assert((BM * BK / 4) % NT == 0, "A load divisibility");
    static_assert((BK * BN / 4) % NT == 0, "B load divisibility");

    __shared__ __align__(16) float As[BK][BM];   // k-major: rows contiguous
    __shared__ __align__(16) float Bs[BK][BN];

    int tid  = threadIdx.x;
    int row0 = blockIdx.x * BM;
    int col0 = blockIdx.y * BN;
    int cg   = tid % NCG;
    int rg   = tid / NCG;

    ULL acc[4][8];
#pragma unroll
    for (int i = 0; i < 4; i++)
#pragma unroll
        for (int j = 0; j < 8; j++) acc[i][j] = 0ull;

    for (int k0 = 0; k0 < K; k0 += BK) {
        // load A tile (transpose to k-major)
        constexpr int A_IT = (BM * BK / 4) / NT;
#pragma unroll
        for (int it = 0; it < A_IT; it++) {
            int idx = tid + it * NT;
            int r = idx / (BK / 4);
            int q = idx % (BK / 4);
            float4 v = *(const float4*)&A[(size_t)(row0 + r) * K + k0 + q * 4];
            As[q * 4 + 0][r] = v.x;
            As[q * 4 + 1][r] = v.y;
            As[q * 4 + 2][r] = v.z;
            As[q * 4 + 3][r] = v.w;
        }
        // load B tile
        constexpr int B_IT = (BK * BN / 4) / NT;
#pragma unroll
        for (int it = 0; it < B_IT; it++) {
            int idx = tid + it * NT;
            int kk = idx / (BN / 4);
            int c  = idx % (BN / 4);
            *(float4*)&Bs[kk][c * 4] =
                *(const float4*)&B[(size_t)(k0 + kk) * N + col0 + c * 4];
        }
        __syncthreads();

#pragma unroll
        for (int kk = 0; kk < BK; kk++) {
            ulonglong2 a01 = *(const ulonglong2*)&As[kk][rg * 8];
            ulonglong2 a23 = *(const ulonglong2*)&As[kk][rg * 8 + 4];
            float4 b0 = *(const float4*)&Bs[kk][cg * 8];
            float4 b1 = *(const float4*)&Bs[kk][cg * 8 + 4];
            ULL bp[8];
            bp[0] = pack2(b0.x, b0.x); bp[1] = pack2(b0.y, b0.y);
            bp[2] = pack2(b0.z, b0.z); bp[3] = pack2(b0.w, b0.w);
            bp[4] = pack2(b1.x, b1.x); bp[5] = pack2(b1.y, b1.y);
            bp[6] = pack2(b1.z, b1.z); bp[7] = pack2(b1.w, b1.w);
#pragma unroll
            for (int j = 0; j < 8; j++) {
                acc[0][j] = fma2(a01.x, bp[j], acc[0][j]);
                acc[1][j] = fma2(a01.y, bp[j], acc[1][j]);
                acc[2][j] = fma2(a23.x, bp[j], acc[2][j]);
                acc[3][j] = fma2(a23.y, bp[j], acc[3][j]);
            }
        }
        __syncthreads();
    }

    // epilogue
    float bb[8];
#pragma unroll
    for (int j = 0; j < 8; j++) bb[j] = bias[col0 + cg * 8 + j];

#pragma unroll
    for (int rp = 0; rp < 4; rp++) {
        float lo[8], hi[8];
#pragma unroll
        for (int j = 0; j < 8; j++) {
            unpack2(acc[rp][j], lo[j], hi[j]);
            lo[j] += bb[j];
            hi[j] += bb[j];
            if (RELU) { lo[j] = fmaxf(lo[j], 0.0f); hi[j] = fmaxf(hi[j], 0.0f); }
        }
        int r_lo = row0 + rg * 8 + rp * 2;
        int r_hi = r_lo + 1;
        float* Clo = &C[(size_t)r_lo * N + col0 + cg * 8];
        float* Chi = &C[(size_t)r_hi * N + col0 + cg * 8];
        *(float4*)(Clo)     = make_float4(lo[0], lo[1], lo[2], lo[3]);
        *(float4*)(Clo + 4) = make_float4(lo[4], lo[5], lo[6], lo[7]);
        *(float4*)(Chi)     = make_float4(hi[0], hi[1], hi[2], hi[3]);
        *(float4*)(Chi + 4) = make_float4(hi[4], hi[5], hi[6], hi[7]);
    }
}

// ---------------- GCN aggregation: h[n] = relu(t[n]/deg + sum_e w*t[col]) ----------------
// one warp per node, 2 features per lane (float2), 4-edge software pipeline
__global__ void aggregate_kernel(const float* __restrict__ t, const int* __restrict__ rowptr,
                                 const int* __restrict__ cnt, const int* __restrict__ col,
                                 const float* __restrict__ wgt, float* __restrict__ h) {
    int warp = (blockIdx.x * blockDim.x + threadIdx.x) >> 5;
    int lane = threadIdx.x & 31;
    if (warp >= N_NODES) return;
    int n = warp;

    float deg = (float)cnt[n] + 1.0f;
    float inv = 1.0f / deg;
    const float2* t2 = (const float2*)t;
    float2 self = t2[(size_t)n * 32 + lane];
    float2 acc;
    acc.x = self.x * inv;
    acc.y = self.y * inv;

    int beg = rowptr[n], end = rowptr[n + 1];
    int e = beg;
    for (; e + 4 <= end; e += 4) {
        int   s0 = col[e],   s1 = col[e + 1], s2 = col[e + 2], s3 = col[e + 3];
        float w0 = wgt[e],   w1 = wgt[e + 1], w2 = wgt[e + 2], w3 = wgt[e + 3];
        float2 v0 = t2[(size_t)s0 * 32 + lane];
        float2 v1 = t2[(size_t)s1 * 32 + lane];
        float2 v2 = t2[(size_t)s2 * 32 + lane];
        float2 v3 = t2[(size_t)s3 * 32 + lane];
        acc.x += w0 * v0.x; acc.y += w0 * v0.y;
        acc.x += w1 * v1.x; acc.y += w1 * v1.y;
        acc.x += w2 * v2.x; acc.y += w2 * v2.y;
        acc.x += w3 * v3.x; acc.y += w3 * v3.y;
    }
    for (; e < end; e++) {
        int s = col[e];
        float w = wgt[e];
        float2 v = t2[(size_t)s * 32 + lane];
        acc.x += w * v.x;
        acc.y += w * v.y;
    }
    float2 out;
    out.x = fmaxf(acc.x, 0.0f);
    out.y = fmaxf(acc.y, 0.0f);
    ((float2*)h)[(size_t)n * 32 + lane] = out;
}

// ---------------- readout: xcat[g] = [segsum(h), x_adduct[g]] ----------------
__global__ void readout_kernel(const float* __restrict__ h, const int* __restrict__ start,
                               const float* __restrict__ x_adduct, float* __restrict__ xcat) {
    int g   = blockIdx.x;
    int tid = threadIdx.x;          // 256
    int f   = tid & 63;
    int sub = tid >> 6;             // 0..3
    int s = start[g], e = start[g + 1];
    float acc = 0.0f;
    for (int n = s + sub; n < e; n += 4) acc += h[(size_t)n * 64 + f];
    __shared__ float red[4][64];
    red[sub][f] = acc;
    __syncthreads();
    if (sub == 0) {
        float v = red[0][f] + red[1][f] + red[2][f] + red[3][f];
        xcat[(size_t)g * 72 + f] = v;
    } else if (sub == 1 && f < ADDUCT) {
        xcat[(size_t)g * 72 + 64 + f] = x_adduct[(size_t)g * ADDUCT + f];
    }
}

// ---------------- final linear: y = z2 @ out_W + out_b ----------------
__global__ void out_layer_kernel(const float* __restrict__ z2, const float* __restrict__ out_W,
                                 const float* __restrict__ out_b, float* __restrict__ y) {
    int g = (blockIdx.x * blockDim.x + threadIdx.x) >> 5;
    int lane = threadIdx.x & 31;
    if (g >= N_GRAPHS) return;
    float acc = 0.0f;
#pragma unroll
    for (int i = lane; i < DENSE; i += 32) acc += z2[(size_t)g * DENSE + i] * out_W[i];
#pragma unroll
    for (int o = 16; o; o >>= 1) acc += __shfl_down_sync(0xffffffffu, acc, o);
    if (lane == 0) y[g] = acc + out_b[0];
}

// ---------------- launch ----------------
extern "C" void kernel_launch(void* const* d_in, const int* in_sizes, int n_in,
                              void* d_out, int out_size) {
    const float* x_mol    = (const float*)d_in[0];
    const float* x_adduct = (const float*)d_in[1];
    const int*   edge_src = (const int*)d_in[2];
    const int*   edge_dst = (const int*)d_in[3];
    const int*   graph_id = (const int*)d_in[4];
    const float* gcn_W    = (const float*)d_in[5];
    const float* gcn_b    = (const float*)d_in[6];
    const float* d1_W     = (const float*)d_in[7];
    const float* d1_b     = (const float*)d_in[8];
    const float* d2_W     = (const float*)d_in[9];
    const float* d2_b     = (const float*)d_in[10];
    const float* out_W    = (const float*)d_in[11];
    const float* out_b    = (const float*)d_in[12];
    float* y = (float*)d_out;

    float *t, *h, *wgt, *xcat, *z1, *z2;
    int *cnt, *rowptr, *cursor, *col, *bsum, *boff, *start;
    cudaGetSymbolAddress((void**)&t,      g_t);
    cudaGetSymbolAddress((void**)&h,      g_h);
    cudaGetSymbolAddress((void**)&cnt,    g_cnt);
    cudaGetSymbolAddress((void**)&rowptr, g_rowptr);
    cudaGetSymbolAddress((void**)&cursor, g_cursor);
    cudaGetSymbolAddress((void**)&col,    g_col);
    cudaGetSymbolAddress((void**)&wgt,    g_wgt);
    cudaGetSymbolAddress((void**)&bsum,   g_bsum);
    cudaGetSymbolAddress((void**)&boff,   g_boff);
    cudaGetSymbolAddress((void**)&start,  g_start);
    cudaGetSymbolAddress((void**)&xcat,   g_xcat);
    cudaGetSymbolAddress((void**)&z1,     g_z1);
    cudaGetSymbolAddress((void**)&z2,     g_z2);

    // ---- degree + CSR build (per call; edges are inputs) ----
    cudaMemsetAsync(cnt, 0, N_NODES * sizeof(int), 0);
    count_deg_kernel<<<N_EDGES / 256, 256>>>(edge_dst, cnt);
    scan_block_kernel<<<N_NODES / 1024, 1024>>>(cnt, rowptr, bsum);
    scan_sums_kernel<<<1, 256>>>(bsum, boff);
    scan_apply_kernel<<<N_NODES / 256, 256>>>(rowptr, boff, cursor);
    fill_csr_kernel<<<N_EDGES / 256, 256>>>(edge_src, edge_dst, cnt, cursor, col, wgt);
    graph_starts_kernel<<<N_NODES / 256, 256>>>(graph_id, start);

    // ---- 3 GCN layers ----
    const float* hin = x_mol;
    for (int L = 0; L < 3; L++) {
        dim3 grid(N_NODES / 128, 1);
        sgemm_kernel<128, 64, false><<<grid, 128>>>(hin, gcn_W + L * UNITS * UNITS,
                                                    gcn_b + L * UNITS, t, UNITS, UNITS);
        aggregate_kernel<<<(N_NODES * 32) / 256, 256>>>(t, rowptr, cnt, col, wgt, h);
        hin = h;
    }

    // ---- readout + dense head ----
    readout_kernel<<<N_GRAPHS, 256>>>(h, start, x_adduct, xcat);
    sgemm_kernel<128, 64, true><<<dim3(N_GRAPHS / 128, DENSE / 64), 128>>>(
        xcat, d1_W, d1_b, z1, UNITS + ADDUCT, DENSE);
    sgemm_kernel<128, 64, true><<<dim3(N_GRAPHS / 128, DENSE / 64), 128>>>(
        z1, d2_W, d2_b, z2, DENSE, DENSE);
    out_layer_kernel<<<(N_GRAPHS * 32) / 256, 256>>>(z2, out_W, out_b, y);
}